// round 1
// baseline (speedup 1.0000x reference)
#include <cuda_runtime.h>
#include <math.h>

#define LL 64
#define NB 8
#define HD 512
#define NV 8192
#define NP 2016                       // L*(L-1)/2 pairs
#define NROW ((NP + 1) * NB)          // 16136 rows (pairs + the (0,0) cell)
#define NROW_PAD (127 * 128)          // 16256, padded to GEMM row tiles
#define NEGV (-1e9f)
#define EPSV 4.5399929762484854e-05f  // exp(-10)

// ------------------------- device scratch -------------------------
__device__ float g_At[LL * NB * HD];      // enc @ W1t[:H]
__device__ float g_Bt[LL * NB * HD];      // enc @ W1t[H:]
__device__ float g_Aw[LL * NB * HD];      // enc @ W1w[:H]
__device__ float g_Bw[LL * NB * HD];      // enc @ W1w[H:]
__device__ float g_hw[NROW_PAD * HD];     // relu hidden for word classifier (33 MB)
__device__ float g_shlog[NP * NB];        // log1p(-p + EPS)
__device__ float g_relog[NP * NB];        // log(p + EPS)
__device__ float g_sum[NROW_PAD];         // sum of exp(logit) per row
__device__ float g_gw[NROW];              // gathered word logit per row
__device__ float g_table[LL * LL * LL * NB];

__device__ __forceinline__ int pidx(int i, int j) {
    // row-major pair index (i outer, j > i)
    return i * (2 * LL - 1 - i) / 2 + (j - i - 1);
}

__device__ __forceinline__ int inv_pair(int p, int& j) {
    int i = 0;
    while (p >= (LL - 1 - i)) { p -= (LL - 1 - i); i++; }
    j = i + 1 + p;
    return i;
}

// ------------------------- init -------------------------
__global__ void fill_init() {
    int idx = blockIdx.x * 256 + threadIdx.x;
    if (idx < LL * LL * LL * NB) g_table[idx] = NEGV;
    if (idx < NROW_PAD) g_sum[idx] = 0.f;
}

// ------------------------- enc projections -------------------------
// C[512,512] = enc_flat[512,512] @ W[koff:koff+512, :]  (W row-major, ld=512)
__global__ void proj_gemm(const float* __restrict__ A, const float* __restrict__ W,
                          int koff, int which) {
    float* C = (which == 0) ? g_At : (which == 1) ? g_Bt : (which == 2) ? g_Aw : g_Bw;
    __shared__ float As[16][64];
    __shared__ float Bs[16][64];
    int tid = threadIdx.x;
    int tc = tid & 15, tr = tid >> 4;
    int rb = blockIdx.y * 64, cb = blockIdx.x * 64;
    float acc[4][4];
#pragma unroll
    for (int i = 0; i < 4; i++)
#pragma unroll
        for (int q = 0; q < 4; q++) acc[i][q] = 0.f;

    for (int k0 = 0; k0 < HD; k0 += 16) {
        for (int l = tid; l < 1024; l += 256) {
            int r = l >> 4, c = l & 15;
            As[c][r] = A[(rb + r) * HD + k0 + c];
        }
        for (int l = tid; l < 1024; l += 256) {
            int r = l >> 6, c = l & 63;
            Bs[r][c] = W[(koff + k0 + r) * HD + cb + c];
        }
        __syncthreads();
#pragma unroll
        for (int kk = 0; kk < 16; kk++) {
            float a[4], b[4];
#pragma unroll
            for (int i = 0; i < 4; i++) a[i] = As[kk][tr * 4 + i];
#pragma unroll
            for (int q = 0; q < 4; q++) b[q] = Bs[kk][tc * 4 + q];
#pragma unroll
            for (int i = 0; i < 4; i++)
#pragma unroll
                for (int q = 0; q < 4; q++) acc[i][q] = fmaf(a[i], b[q], acc[i][q]);
        }
        __syncthreads();
    }
#pragma unroll
    for (int i = 0; i < 4; i++)
#pragma unroll
        for (int q = 0; q < 4; q++)
            C[(rb + tr * 4 + i) * HD + cb + tc * 4 + q] = acc[i][q];
}

// ------------------------- per-pair MLP heads -------------------------
// One block per pair (block NP == the (0,0) cell). Warp w handles batch w.
__global__ void pair_kernel(const float* __restrict__ b1t, const float* __restrict__ W2t,
                            const float* __restrict__ b2t, const float* __restrict__ b1w) {
    int p = blockIdx.x;
    int i = 0, j = 0;
    if (p < NP) i = inv_pair(p, j);
    int w = threadIdx.x >> 5;
    int lane = threadIdx.x & 31;
    const float* Ar = &g_Aw[(i * NB + w) * HD];
    const float* Br = &g_Bw[(j * NB + w) * HD];
    const float* At = &g_At[(i * NB + w) * HD];
    const float* Bt = &g_Bt[(j * NB + w) * HD];
    float* hwrow = &g_hw[(p * NB + w) * HD];
    float part = 0.f;
#pragma unroll 4
    for (int t = 0; t < 16; t++) {
        int h = lane + t * 32;
        float hw = Ar[h] + Br[h] + b1w[h];
        hwrow[h] = fmaxf(hw, 0.f);
        if (p < NP) {
            float ht = fmaxf(At[h] + Bt[h] + b1t[h], 0.f);
            part = fmaf(ht, W2t[h], part);
        }
    }
    if (p < NP) {
#pragma unroll
        for (int o = 16; o; o >>= 1) part += __shfl_xor_sync(0xffffffffu, part, o);
        if (lane == 0) {
            float z = part + b2t[0];
            float s = 1.f / (1.f + expf(-z));
            g_shlog[p * NB + w] = log1pf(-s + EPSV);
            g_relog[p * NB + w] = logf(s + EPSV);
        }
    }
}

// ------------------------- fused big GEMM + sum(exp) -------------------------
// C = hw[16256,512] @ W2w[512,8192]; per row accumulate sum_v exp(c + b2w[v]).
// grid (127, 2): blockIdx.y picks a 4096-wide V half; partials combine via atomicAdd.
__global__ void __launch_bounds__(256, 2) gemm_lse(const float* __restrict__ W2w,
                                                   const float* __restrict__ b2w) {
    __shared__ float As[16][128];
    __shared__ float Bs[16][128];
    __shared__ float red[128][17];
    int tid = threadIdx.x;
    int tcol = tid & 15, trow = tid >> 4;
    int rowBase = blockIdx.x * 128;
    int vBase = blockIdx.y * (NV / 2);

    float s_exp[8];
#pragma unroll
    for (int i = 0; i < 8; i++) s_exp[i] = 0.f;

    for (int vc = 0; vc < NV / 2; vc += 128) {
        int v0 = vBase + vc;
        float bw[8];
#pragma unroll
        for (int q = 0; q < 8; q++) bw[q] = b2w[v0 + tcol * 8 + q];
        float acc[8][8];
#pragma unroll
        for (int i = 0; i < 8; i++)
#pragma unroll
            for (int q = 0; q < 8; q++) acc[i][q] = 0.f;

        for (int k0 = 0; k0 < HD; k0 += 16) {
#pragma unroll
            for (int li = 0; li < 2; li++) {
                int l = tid + li * 256;
                int r = l >> 2, c4 = l & 3;
                float4 v = *(const float4*)(&g_hw[(rowBase + r) * HD + k0 + c4 * 4]);
                As[c4 * 4 + 0][r] = v.x;
                As[c4 * 4 + 1][r] = v.y;
                As[c4 * 4 + 2][r] = v.z;
                As[c4 * 4 + 3][r] = v.w;
            }
#pragma unroll
            for (int li = 0; li < 2; li++) {
                int l = tid + li * 256;
                int r = l >> 5, c4 = l & 31;
                *(float4*)(&Bs[r][c4 * 4]) =
                    *(const float4*)(&W2w[(k0 + r) * NV + v0 + c4 * 4]);
            }
            __syncthreads();
#pragma unroll
            for (int kk = 0; kk < 16; kk++) {
                float a[8], b[8];
#pragma unroll
                for (int i = 0; i < 8; i++) a[i] = As[kk][trow * 8 + i];
#pragma unroll
                for (int q = 0; q < 8; q++) b[q] = Bs[kk][tcol * 8 + q];
#pragma unroll
                for (int i = 0; i < 8; i++)
#pragma unroll
                    for (int q = 0; q < 8; q++) acc[i][q] = fmaf(a[i], b[q], acc[i][q]);
            }
            __syncthreads();
        }
        // epilogue: logits are O(1) here (weights ~0.02 scale) -> direct exp is safe
#pragma unroll
        for (int i = 0; i < 8; i++) {
            float t = 0.f;
#pragma unroll
            for (int q = 0; q < 8; q++) t += __expf(acc[i][q] + bw[q]);
            s_exp[i] += t;
        }
    }
#pragma unroll
    for (int i = 0; i < 8; i++) red[trow * 8 + i][tcol] = s_exp[i];
    __syncthreads();
    if (tid < 128) {
        float s = 0.f;
#pragma unroll
        for (int c = 0; c < 16; c++) s += red[tid][c];
        atomicAdd(&g_sum[rowBase + tid], s);
    }
}

// ------------------------- gathered word logit -------------------------
__global__ void gather_kernel(const int* __restrict__ sentence,
                              const float* __restrict__ W2w,
                              const float* __restrict__ b2w) {
    int row = blockIdx.x * 8 + (threadIdx.x >> 5);
    int lane = threadIdx.x & 31;
    if (row >= NROW) return;
    int p = row >> 3, b = row & 7;
    int jw;
    if (p < NP) { int j; inv_pair(p, j); jw = (j + 1 < LL) ? j + 1 : 0; }
    else jw = 1;  // (0,0) cell uses sentence[1]
    int word = sentence[jw * NB + b];
    const float* hwrow = &g_hw[row * HD];
    float part = 0.f;
#pragma unroll 4
    for (int t = 0; t < 16; t++) {
        int h = lane + t * 32;
        part = fmaf(hwrow[h], W2w[h * NV + word], part);
    }
#pragma unroll
    for (int o = 16; o; o >>= 1) part += __shfl_xor_sync(0xffffffffu, part, o);
    if (lane == 0) g_gw[row] = part + b2w[word];
}

// ------------------------- DP base cells -------------------------
__global__ void base_kernel() {
    int idx = blockIdx.x * 256 + threadIdx.x;
    if (idx < NP * NB) {
        int p = idx >> 3, b = idx & 7;
        int j;
        int i = inv_pair(p, j);
        if (j <= LL - 2) {  // base cells: j <= n-1 = 62
            float lse = logf(g_sum[idx]);
            g_table[((i * LL + j) * LL + (j + 1)) * NB + b] =
                g_shlog[idx] + g_gw[idx] - lse;
        }
    } else if (idx < NP * NB + NB) {
        int b = idx - NP * NB;
        int r = NP * NB + b;
        g_table[(0 * LL + 1) * NB + b] = g_gw[r] - logf(g_sum[r]);  // table[0,0,1]
    }
}

// ------------------------- inside recursion, one gap per launch -------------------------
__global__ void dp_step(int gap) {
    int iv = blockIdx.x;
    int jv = iv + gap;
    int nk = gap - 1;
    __shared__ float right[62 * 8];
    int tid = threadIdx.x;
    for (int m = tid; m < nk * 8; m += 512) {
        int d = m >> 3, b = m & 7;
        int k = iv + 1 + d;
        right[m] = g_table[((iv * LL + k) * LL + jv) * NB + b] +
                   g_relog[pidx(k, jv) * NB + b];
    }
    __syncthreads();
    int b = tid & 7, l = tid >> 3;
    const float* base = &g_table[(l * LL + iv) * LL * NB + b];
    float mx = -3.0e38f, s = 0.f;
    for (int d = 0; d < nk; d++) {
        int k = iv + 1 + d;
        float x = base[k * NB] + right[d * 8 + b];
        if (x > mx) { s = s * __expf(mx - x) + 1.f; mx = x; }
        else s += __expf(x - mx);
    }
    g_table[((l * LL + iv) * LL + jv) * NB + b] = mx + logf(s);
}

__global__ void copy_out(float* __restrict__ out) {
    int b = threadIdx.x;
    if (b < NB) out[b] = g_table[(0 * LL + (LL - 1)) * NB + b];  // table[0,0,63]
}

// ------------------------- launch -------------------------
extern "C" void kernel_launch(void* const* d_in, const int* in_sizes, int n_in,
                              void* d_out, int out_size) {
    const float* enc = (const float*)d_in[0];
    const int* sentence = (const int*)d_in[1];
    const float* W1t = (const float*)d_in[2];
    const float* b1t = (const float*)d_in[3];
    const float* W2t = (const float*)d_in[4];
    const float* b2t = (const float*)d_in[5];
    const float* W1w = (const float*)d_in[6];
    const float* b1w = (const float*)d_in[7];
    const float* W2w = (const float*)d_in[8];
    const float* b2w = (const float*)d_in[9];
    float* out = (float*)d_out;

    fill_init<<<8192, 256>>>();

    dim3 pg(8, 8);
    proj_gemm<<<pg, 256>>>(enc, W1t, 0, 0);
    proj_gemm<<<pg, 256>>>(enc, W1t, HD, 1);
    proj_gemm<<<pg, 256>>>(enc, W1w, 0, 2);
    proj_gemm<<<pg, 256>>>(enc, W1w, HD, 3);

    pair_kernel<<<NP + 1, 256>>>(b1t, W2t, b2t, b1w);

    gemm_lse<<<dim3(127, 2), 256>>>(W2w, b2w);

    gather_kernel<<<(NROW + 7) / 8, 256>>>(sentence, W2w, b2w);
    base_kernel<<<64, 256>>>();

    for (int gap = 2; gap <= LL - 1; gap++)
        dp_step<<<LL - gap, 512>>>(gap);

    copy_out<<<1, 32>>>(out);
}

// round 5
// speedup vs baseline: 3.2271x; 3.2271x over previous
#include <cuda_runtime.h>
#include <cuda_bf16.h>
#include <mma.h>
#include <math.h>

#define LL 64
#define NB 8
#define HD 512
#define NV 8192
#define NP 2016                       // L*(L-1)/2 pairs
#define NROW ((NP + 1) * NB)          // 16136 rows (pairs + the (0,0) cell)
#define NROW_PAD (127 * 128)          // 16256, padded to GEMM row tiles
#define NEGV (-1e9f)
#define EPSV 4.5399929762484854e-05f  // exp(-10)

using namespace nvcuda;

// ------------------------- device scratch -------------------------
__device__ float g_At[LL * NB * HD];      // enc @ W1t[:H]
__device__ float g_Bt[LL * NB * HD];      // enc @ W1t[H:]
__device__ float g_Aw[LL * NB * HD];      // enc @ W1w[:H]
__device__ float g_Bw[LL * NB * HD];      // enc @ W1w[H:]
__device__ __nv_bfloat16 g_hwb[NROW_PAD * HD];   // relu hidden (bf16) for word head
__device__ __nv_bfloat16 g_W2wb[HD * NV];        // W2w in bf16
__device__ float g_shlog[NP * NB];        // log1p(-p + EPS)
__device__ float g_relog[NP * NB];        // log(p + EPS)
__device__ float g_sum[NROW_PAD];         // sum of exp(logit) per row
__device__ float g_gw[NROW];              // gathered word logit per row
__device__ float g_table[LL * LL * LL * NB];

__device__ __forceinline__ int pidx(int i, int j) {
    return i * (2 * LL - 1 - i) / 2 + (j - i - 1);
}

__device__ __forceinline__ int inv_pair(int p, int& j) {
    int i = 0;
    while (p >= (LL - 1 - i)) { p -= (LL - 1 - i); i++; }
    j = i + 1 + p;
    return i;
}

// ------------------------- init -------------------------
__global__ void fill_init() {
    int idx = blockIdx.x * 256 + threadIdx.x;
    if (idx < LL * LL * LL * NB) g_table[idx] = NEGV;
    if (idx < NROW_PAD) g_sum[idx] = 0.f;
    if (idx < (NROW_PAD - NROW) * HD) g_hwb[NROW * HD + idx] = __float2bfloat16(0.f);
}

// ------------------------- W2w -> bf16 -------------------------
__global__ void convertW(const float* __restrict__ W) {
    int i = (blockIdx.x * 256 + threadIdx.x) * 4;
    float4 v = *(const float4*)(W + i);
    __nv_bfloat16 o[4];
    o[0] = __float2bfloat16(v.x);
    o[1] = __float2bfloat16(v.y);
    o[2] = __float2bfloat16(v.z);
    o[3] = __float2bfloat16(v.w);
    *(unsigned long long*)(&g_W2wb[i]) = *(unsigned long long*)o;
}

// ------------------------- enc projections (all 4 in one launch) -------------------------
__global__ void proj_gemm(const float* __restrict__ A, const float* __restrict__ W1t,
                          const float* __restrict__ W1w) {
    int which = blockIdx.z;
    const float* W = (which < 2) ? W1t : W1w;
    int koff = (which & 1) * HD;
    float* C = (which == 0) ? g_At : (which == 1) ? g_Bt : (which == 2) ? g_Aw : g_Bw;
    __shared__ float As[16][64];
    __shared__ float Bs[16][64];
    int tid = threadIdx.x;
    int tc = tid & 15, tr = tid >> 4;
    int rb = blockIdx.y * 64, cb = blockIdx.x * 64;
    float acc[4][4];
    for (int i = 0; i < 4; i++)
        for (int q = 0; q < 4; q++) acc[i][q] = 0.f;

    for (int k0 = 0; k0 < HD; k0 += 16) {
        for (int l = tid; l < 1024; l += 256) {
            int r = l >> 4, c = l & 15;
            As[c][r] = A[(rb + r) * HD + k0 + c];
        }
        for (int l = tid; l < 1024; l += 256) {
            int r = l >> 6, c = l & 63;
            Bs[r][c] = W[(koff + k0 + r) * HD + cb + c];
        }
        __syncthreads();
        for (int kk = 0; kk < 16; kk++) {
            float av[4], bv[4];
            for (int i = 0; i < 4; i++) av[i] = As[kk][tr * 4 + i];
            for (int q = 0; q < 4; q++) bv[q] = Bs[kk][tc * 4 + q];
            for (int i = 0; i < 4; i++)
                for (int q = 0; q < 4; q++) acc[i][q] = fmaf(av[i], bv[q], acc[i][q]);
        }
        __syncthreads();
    }
    for (int i = 0; i < 4; i++)
        for (int q = 0; q < 4; q++)
            C[(rb + tr * 4 + i) * HD + cb + tc * 4 + q] = acc[i][q];
}

// ------------------------- per-pair MLP heads -------------------------
__global__ void pair_kernel(const float* __restrict__ b1t, const float* __restrict__ W2t,
                            const float* __restrict__ b2t, const float* __restrict__ b1w) {
    int p = blockIdx.x;
    int i = 0, j = 0;
    if (p < NP) i = inv_pair(p, j);
    int w = threadIdx.x >> 5;
    int lane = threadIdx.x & 31;
    const float* Ar = &g_Aw[(i * NB + w) * HD];
    const float* Br = &g_Bw[(j * NB + w) * HD];
    const float* At = &g_At[(i * NB + w) * HD];
    const float* Bt = &g_Bt[(j * NB + w) * HD];
    __nv_bfloat16* hwrow = &g_hwb[(p * NB + w) * HD];
    float part = 0.f;
    for (int t = 0; t < 16; t++) {
        int h = lane + t * 32;
        float hw = fmaxf(Ar[h] + Br[h] + b1w[h], 0.f);
        hwrow[h] = __float2bfloat16(hw);
        if (p < NP) {
            float ht = fmaxf(At[h] + Bt[h] + b1t[h], 0.f);
            part = fmaf(ht, W2t[h], part);
        }
    }
    if (p < NP) {
        for (int o = 16; o; o >>= 1) part += __shfl_xor_sync(0xffffffffu, part, o);
        if (lane == 0) {
            float z = part + b2t[0];
            float s = 1.f / (1.f + expf(-z));
            g_shlog[p * NB + w] = log1pf(-s + EPSV);
            g_relog[p * NB + w] = logf(s + EPSV);
        }
    }
}

// ------------------------- wmma GEMM + sum(exp) -------------------------
// C = hwb[16256,512] @ W2wb[512,8192] (bf16 -> f32); per row accumulate
// sum_v exp(c + b2w[v]) into g_sum via atomicAdd (64 column blocks).
// Tiles: BM=128, BN=128, BK=32. 8 warps as 2 (m) x 4 (n); warp tile 64x32
// = 4 (mt) x 2 (nt) wmma 16x16x16 fragments.
#define AS_LD 48
#define BS_LD 144
__global__ void __launch_bounds__(256) gemm_lse_wmma(const float* __restrict__ b2w) {
    __shared__ __align__(128) __nv_bfloat16 As[128 * AS_LD];
    __shared__ __align__(128) __nv_bfloat16 Bs[32 * BS_LD];
    __shared__ __align__(128) float stage[8 * 256];   // 1KB per warp
    int tid = threadIdx.x;
    int wid = tid >> 5, lane = tid & 31;
    int wm = wid >> 2, wn = wid & 3;
    int rowBase = blockIdx.x * 128;
    int v0 = blockIdx.y * 128;

    wmma::fragment<wmma::accumulator, 16, 16, 16, float> acc[4][2];
    for (int mt = 0; mt < 4; mt++)
        for (int nt = 0; nt < 2; nt++) wmma::fill_fragment(acc[mt][nt], 0.f);

    for (int k0 = 0; k0 < HD; k0 += 32) {
        // A tile 128x32 (2 x uint4 per thread)
        for (int l = 0; l < 2; l++) {
            int idx = tid + l * 256;
            int r = idx >> 2, c8 = (idx & 3) * 8;
            *(uint4*)(&As[r * AS_LD + c8]) =
                *(const uint4*)(&g_hwb[(rowBase + r) * HD + k0 + c8]);
        }
        // B tile 32x128 k-major (2 x uint4 per thread)
        for (int l = 0; l < 2; l++) {
            int idx = tid + l * 256;
            int kk = idx >> 4, n8 = (idx & 15) * 8;
            *(uint4*)(&Bs[kk * BS_LD + n8]) =
                *(const uint4*)(&g_W2wb[(k0 + kk) * NV + v0 + n8]);
        }
        __syncthreads();
        for (int kk = 0; kk < 32; kk += 16) {
            wmma::fragment<wmma::matrix_a, 16, 16, 16, __nv_bfloat16, wmma::row_major> af[4];
            wmma::fragment<wmma::matrix_b, 16, 16, 16, __nv_bfloat16, wmma::row_major> bf[2];
            for (int mt = 0; mt < 4; mt++)
                wmma::load_matrix_sync(af[mt], &As[(wm * 64 + mt * 16) * AS_LD + kk], AS_LD);
            for (int nt = 0; nt < 2; nt++)
                wmma::load_matrix_sync(bf[nt], &Bs[kk * BS_LD + wn * 32 + nt * 16], BS_LD);
            for (int mt = 0; mt < 4; mt++)
                for (int nt = 0; nt < 2; nt++)
                    wmma::mma_sync(acc[mt][nt], af[mt], bf[nt], acc[mt][nt]);
        }
        __syncthreads();
    }

    // epilogue: stage each 16x16 tile, exp + row-reduce, atomicAdd per row
    float* st = &stage[wid * 256];
    int r = lane & 15, half = lane >> 4;
    float rs[4];
    for (int mt = 0; mt < 4; mt++) rs[mt] = 0.f;
    for (int mt = 0; mt < 4; mt++) {
        for (int nt = 0; nt < 2; nt++) {
            wmma::store_matrix_sync(st, acc[mt][nt], 16, wmma::mem_row_major);
            __syncwarp();
            int cb = v0 + wn * 32 + nt * 16 + half * 8;
            float s = 0.f;
            for (int c = 0; c < 8; c++)
                s += __expf(st[r * 16 + half * 8 + c] + b2w[cb + c]);
            s += __shfl_xor_sync(0xffffffffu, s, 16);
            rs[mt] += s;
            __syncwarp();
        }
    }
    if (lane < 16) {
        for (int mt = 0; mt < 4; mt++)
            atomicAdd(&g_sum[rowBase + wm * 64 + mt * 16 + lane], rs[mt]);
    }
}

// ------------------------- gathered word logit -------------------------
__global__ void gather_kernel(const int* __restrict__ sentence,
                              const float* __restrict__ b2w) {
    int row = blockIdx.x * 8 + (threadIdx.x >> 5);
    int lane = threadIdx.x & 31;
    if (row >= NROW) return;
    int p = row >> 3, b = row & 7;
    int jw;
    if (p < NP) { int j; inv_pair(p, j); jw = (j + 1 < LL) ? j + 1 : 0; }
    else jw = 1;  // (0,0) cell uses sentence[1]
    int word = sentence[jw * NB + b];
    const __nv_bfloat16* hwrow = &g_hwb[row * HD];
    float part = 0.f;
    for (int tt = 0; tt < 16; tt++) {
        int h = lane + tt * 32;
        part = fmaf(__bfloat162float(hwrow[h]),
                    __bfloat162float(g_W2wb[h * NV + word]), part);
    }
    for (int o = 16; o; o >>= 1) part += __shfl_xor_sync(0xffffffffu, part, o);
    if (lane == 0) g_gw[row] = part + b2w[word];
}

// ------------------------- DP base cells -------------------------
__global__ void base_kernel() {
    int idx = blockIdx.x * 256 + threadIdx.x;
    if (idx < NP * NB) {
        int p = idx >> 3, b = idx & 7;
        int j;
        int i = inv_pair(p, j);
        if (j <= LL - 2) {
            float lse = logf(g_sum[idx]);
            g_table[((i * LL + j) * LL + (j + 1)) * NB + b] =
                g_shlog[idx] + g_gw[idx] - lse;
        }
    } else if (idx < NP * NB + NB) {
        int b = idx - NP * NB;
        int rr = NP * NB + b;
        g_table[(0 * LL + 1) * NB + b] = g_gw[rr] - logf(g_sum[rr]);
    }
}

// ------------------------- inside recursion, one gap per launch -------------------------
__global__ void dp_step(int gap) {
    int iv = blockIdx.x;
    int jv = iv + gap;
    int nk = gap - 1;
    __shared__ float right[62 * 8];
    int tid = threadIdx.x;
    for (int m = tid; m < nk * 8; m += 512) {
        int d = m >> 3, b = m & 7;
        int k = iv + 1 + d;
        right[m] = g_table[((iv * LL + k) * LL + jv) * NB + b] +
                   g_relog[pidx(k, jv) * NB + b];
    }
    __syncthreads();
    int b = tid & 7, l = tid >> 3;
    const float* base = &g_table[(l * LL + iv) * LL * NB + b];
    float mx = -3.0e38f, s = 0.f;
    for (int d = 0; d < nk; d++) {
        int k = iv + 1 + d;
        float x = base[k * NB] + right[d * 8 + b];
        if (x > mx) { s = s * __expf(mx - x) + 1.f; mx = x; }
        else s += __expf(x - mx);
    }
    g_table[((l * LL + iv) * LL + jv) * NB + b] = mx + logf(s);
}

__global__ void copy_out(float* __restrict__ out) {
    int b = threadIdx.x;
    if (b < NB) out[b] = g_table[(0 * LL + (LL - 1)) * NB + b];
}

// ------------------------- launch -------------------------
extern "C" void kernel_launch(void* const* d_in, const int* in_sizes, int n_in,
                              void* d_out, int out_size) {
    const float* enc = (const float*)d_in[0];
    const int* sentence = (const int*)d_in[1];
    const float* W1t = (const float*)d_in[2];
    const float* b1t = (const float*)d_in[3];
    const float* W2t = (const float*)d_in[4];
    const float* b2t = (const float*)d_in[5];
    const float* W1w = (const float*)d_in[6];
    const float* b1w = (const float*)d_in[7];
    const float* W2w = (const float*)d_in[8];
    const float* b2w = (const float*)d_in[9];
    float* out = (float*)d_out;

    fill_init<<<8192, 256>>>();
    convertW<<<(HD * NV) / (256 * 4), 256>>>(W2w);

    proj_gemm<<<dim3(8, 8, 4), 256>>>(enc, W1t, W1w);

    pair_kernel<<<NP + 1, 256>>>(b1t, W2t, b2t, b1w);

    gemm_lse_wmma<<<dim3(127, 64), 256>>>(b2w);

    gather_kernel<<<(NROW + 7) / 8, 256>>>(sentence, b2w);
    base_kernel<<<64, 256>>>();

    for (int gap = 2; gap <= LL - 1; gap++)
        dp_step<<<LL - gap, 512>>>(gap);

    copy_out<<<1, 32>>>(out);
}

// round 6
// speedup vs baseline: 3.4319x; 1.0635x over previous
#include <cuda_runtime.h>
#include <cuda_bf16.h>
#include <mma.h>
#include <math.h>

#define LL 64
#define NB 8
#define HD 512
#define NV 8192
#define NP 2016                       // L*(L-1)/2 pairs
#define NROW ((NP + 1) * NB)          // 16136 rows (pairs + the (0,0) cell)
#define NROW_PAD (127 * 128)          // 16256, padded to GEMM row tiles
#define NEGV (-1e9f)
#define EPSV 4.5399929762484854e-05f  // exp(-10)

using namespace nvcuda;

// ------------------------- device scratch -------------------------
__device__ float g_At[LL * NB * HD];      // enc @ W1t[:H]
__device__ float g_Bt[LL * NB * HD];      // enc @ W1t[H:]
__device__ float g_Aw[LL * NB * HD];      // enc @ W1w[:H]
__device__ float g_Bw[LL * NB * HD];      // enc @ W1w[H:]
__device__ __nv_bfloat16 g_hwb[NROW_PAD * HD];   // relu hidden (bf16) for word head
__device__ __nv_bfloat16 g_W2wb[HD * NV];        // W2w in bf16
__device__ float g_shlog[NP * NB];        // log1p(-p + EPS)
__device__ float g_relog[NP * NB];        // log(p + EPS)
__device__ float g_sum[NROW_PAD];         // sum of exp(logit) per row
__device__ float g_gw[NROW];              // gathered word logit per row
__device__ float g_table[LL * LL * LL * NB];
__device__ int g_bar[LL];                 // per-gap arrival counters (zeroed each call)

__device__ __forceinline__ int pidx(int i, int j) {
    return i * (2 * LL - 1 - i) / 2 + (j - i - 1);
}

__device__ __forceinline__ int inv_pair(int p, int& j) {
    int i = 0;
    while (p >= (LL - 1 - i)) { p -= (LL - 1 - i); i++; }
    j = i + 1 + p;
    return i;
}

// ------------------------- init -------------------------
__global__ void fill_init() {
    int idx = blockIdx.x * 256 + threadIdx.x;
    if (idx < LL * LL * LL * NB) g_table[idx] = NEGV;
    if (idx < NROW_PAD) g_sum[idx] = 0.f;
    if (idx < (NROW_PAD - NROW) * HD) g_hwb[NROW * HD + idx] = __float2bfloat16(0.f);
    if (idx < LL) g_bar[idx] = 0;
}

// ------------------------- W2w -> bf16 -------------------------
__global__ void convertW(const float* __restrict__ W) {
    int i = (blockIdx.x * 256 + threadIdx.x) * 4;
    float4 v = *(const float4*)(W + i);
    __nv_bfloat16 o[4];
    o[0] = __float2bfloat16(v.x);
    o[1] = __float2bfloat16(v.y);
    o[2] = __float2bfloat16(v.z);
    o[3] = __float2bfloat16(v.w);
    *(unsigned long long*)(&g_W2wb[i]) = *(unsigned long long*)o;
}

// ------------------------- enc projections (all 4 in one launch) -------------------------
__global__ void proj_gemm(const float* __restrict__ A, const float* __restrict__ W1t,
                          const float* __restrict__ W1w) {
    int which = blockIdx.z;
    const float* W = (which < 2) ? W1t : W1w;
    int koff = (which & 1) * HD;
    float* C = (which == 0) ? g_At : (which == 1) ? g_Bt : (which == 2) ? g_Aw : g_Bw;
    __shared__ float As[16][64];
    __shared__ float Bs[16][64];
    int tid = threadIdx.x;
    int tc = tid & 15, tr = tid >> 4;
    int rb = blockIdx.y * 64, cb = blockIdx.x * 64;
    float acc[4][4];
    for (int i = 0; i < 4; i++)
        for (int q = 0; q < 4; q++) acc[i][q] = 0.f;

    for (int k0 = 0; k0 < HD; k0 += 16) {
        for (int l = tid; l < 1024; l += 256) {
            int r = l >> 4, c = l & 15;
            As[c][r] = A[(rb + r) * HD + k0 + c];
        }
        for (int l = tid; l < 1024; l += 256) {
            int r = l >> 6, c = l & 63;
            Bs[r][c] = W[(koff + k0 + r) * HD + cb + c];
        }
        __syncthreads();
        for (int kk = 0; kk < 16; kk++) {
            float av[4], bv[4];
            for (int i = 0; i < 4; i++) av[i] = As[kk][tr * 4 + i];
            for (int q = 0; q < 4; q++) bv[q] = Bs[kk][tc * 4 + q];
            for (int i = 0; i < 4; i++)
                for (int q = 0; q < 4; q++) acc[i][q] = fmaf(av[i], bv[q], acc[i][q]);
        }
        __syncthreads();
    }
    for (int i = 0; i < 4; i++)
        for (int q = 0; q < 4; q++)
            C[(rb + tr * 4 + i) * HD + cb + tc * 4 + q] = acc[i][q];
}

// ------------------------- per-pair MLP heads -------------------------
__global__ void pair_kernel(const float* __restrict__ b1t, const float* __restrict__ W2t,
                            const float* __restrict__ b2t, const float* __restrict__ b1w) {
    int p = blockIdx.x;
    int i = 0, j = 0;
    if (p < NP) i = inv_pair(p, j);
    int w = threadIdx.x >> 5;
    int lane = threadIdx.x & 31;
    const float* Ar = &g_Aw[(i * NB + w) * HD];
    const float* Br = &g_Bw[(j * NB + w) * HD];
    const float* At = &g_At[(i * NB + w) * HD];
    const float* Bt = &g_Bt[(j * NB + w) * HD];
    __nv_bfloat16* hwrow = &g_hwb[(p * NB + w) * HD];
    float part = 0.f;
    for (int t = 0; t < 16; t++) {
        int h = lane + t * 32;
        float hw = fmaxf(Ar[h] + Br[h] + b1w[h], 0.f);
        hwrow[h] = __float2bfloat16(hw);
        if (p < NP) {
            float ht = fmaxf(At[h] + Bt[h] + b1t[h], 0.f);
            part = fmaf(ht, W2t[h], part);
        }
    }
    if (p < NP) {
        for (int o = 16; o; o >>= 1) part += __shfl_xor_sync(0xffffffffu, part, o);
        if (lane == 0) {
            float z = part + b2t[0];
            float s = 1.f / (1.f + expf(-z));
            g_shlog[p * NB + w] = log1pf(-s + EPSV);
            g_relog[p * NB + w] = logf(s + EPSV);
        }
    }
}

// ------------------------- wmma GEMM + sum(exp), reg-prefetch double buffer ----
// C = hwb[16256,512] @ W2wb[512,8192] (bf16 -> f32); per row accumulate
// sum_v exp(c + b2w[v]) into g_sum via atomicAdd (64 column blocks).
// Tiles: BM=128, BN=128, BK=32. 8 warps as 2 (m) x 4 (n); warp tile 64x32.
// Next k-tile is prefetched into registers before compute of the current tile.
#define AS_LD 48
#define BS_LD 144
__global__ void __launch_bounds__(256) gemm_lse_wmma(const float* __restrict__ b2w) {
    __shared__ __align__(128) __nv_bfloat16 As[128 * AS_LD];
    __shared__ __align__(128) __nv_bfloat16 Bs[32 * BS_LD];
    __shared__ __align__(128) float stage[8 * 256];   // 1KB per warp
    int tid = threadIdx.x;
    int wid = tid >> 5, lane = tid & 31;
    int wm = wid >> 2, wn = wid & 3;
    int rowBase = blockIdx.x * 128;
    int v0 = blockIdx.y * 128;

    // per-thread load coordinates
    int ar0 = tid >> 2, ac0 = (tid & 3) * 8;              // A: idx = tid
    int ar1 = (tid + 256) >> 2, ac1 = ((tid + 256) & 3) * 8;
    int bk0 = tid >> 4, bn0 = (tid & 15) * 8;             // B: idx = tid
    int bk1 = (tid + 256) >> 4, bn1 = ((tid + 256) & 15) * 8;

    wmma::fragment<wmma::accumulator, 16, 16, 16, float> acc[4][2];
    for (int mt = 0; mt < 4; mt++)
        for (int nt = 0; nt < 2; nt++) wmma::fill_fragment(acc[mt][nt], 0.f);

    // prologue: prefetch k-tile 0 into registers
    uint4 pa0 = *(const uint4*)(&g_hwb[(rowBase + ar0) * HD + ac0]);
    uint4 pa1 = *(const uint4*)(&g_hwb[(rowBase + ar1) * HD + ac1]);
    uint4 pb0 = *(const uint4*)(&g_W2wb[bk0 * NV + v0 + bn0]);
    uint4 pb1 = *(const uint4*)(&g_W2wb[bk1 * NV + v0 + bn1]);

    for (int kt = 0; kt < 16; kt++) {
        // store the prefetched tile to smem
        *(uint4*)(&As[ar0 * AS_LD + ac0]) = pa0;
        *(uint4*)(&As[ar1 * AS_LD + ac1]) = pa1;
        *(uint4*)(&Bs[bk0 * BS_LD + bn0]) = pb0;
        *(uint4*)(&Bs[bk1 * BS_LD + bn1]) = pb1;
        __syncthreads();
        // issue next tile's loads (latency hidden behind compute below)
        if (kt + 1 < 16) {
            int k0 = (kt + 1) * 32;
            pa0 = *(const uint4*)(&g_hwb[(rowBase + ar0) * HD + k0 + ac0]);
            pa1 = *(const uint4*)(&g_hwb[(rowBase + ar1) * HD + k0 + ac1]);
            pb0 = *(const uint4*)(&g_W2wb[(k0 + bk0) * NV + v0 + bn0]);
            pb1 = *(const uint4*)(&g_W2wb[(k0 + bk1) * NV + v0 + bn1]);
        }
        for (int kk = 0; kk < 32; kk += 16) {
            wmma::fragment<wmma::matrix_a, 16, 16, 16, __nv_bfloat16, wmma::row_major> af[4];
            wmma::fragment<wmma::matrix_b, 16, 16, 16, __nv_bfloat16, wmma::row_major> bf[2];
            for (int mt = 0; mt < 4; mt++)
                wmma::load_matrix_sync(af[mt], &As[(wm * 64 + mt * 16) * AS_LD + kk], AS_LD);
            for (int nt = 0; nt < 2; nt++)
                wmma::load_matrix_sync(bf[nt], &Bs[kk * BS_LD + wn * 32 + nt * 16], BS_LD);
            for (int mt = 0; mt < 4; mt++)
                for (int nt = 0; nt < 2; nt++)
                    wmma::mma_sync(acc[mt][nt], af[mt], bf[nt], acc[mt][nt]);
        }
        __syncthreads();
    }

    // epilogue: stage each 16x16 tile, exp + row-reduce, atomicAdd per row
    float* st = &stage[wid * 256];
    int r = lane & 15, half = lane >> 4;
    float rs[4];
    for (int mt = 0; mt < 4; mt++) rs[mt] = 0.f;
    for (int mt = 0; mt < 4; mt++) {
        for (int nt = 0; nt < 2; nt++) {
            wmma::store_matrix_sync(st, acc[mt][nt], 16, wmma::mem_row_major);
            __syncwarp();
            int cb = v0 + wn * 32 + nt * 16 + half * 8;
            float s = 0.f;
            for (int c = 0; c < 8; c++)
                s += __expf(st[r * 16 + half * 8 + c] + b2w[cb + c]);
            s += __shfl_xor_sync(0xffffffffu, s, 16);
            rs[mt] += s;
            __syncwarp();
        }
    }
    if (lane < 16) {
        for (int mt = 0; mt < 4; mt++)
            atomicAdd(&g_sum[rowBase + wm * 64 + mt * 16 + lane], rs[mt]);
    }
}

// ------------------------- gathered word logit -------------------------
__global__ void gather_kernel(const int* __restrict__ sentence,
                              const float* __restrict__ b2w) {
    int row = blockIdx.x * 8 + (threadIdx.x >> 5);
    int lane = threadIdx.x & 31;
    if (row >= NROW) return;
    int p = row >> 3, b = row & 7;
    int jw;
    if (p < NP) { int j; inv_pair(p, j); jw = (j + 1 < LL) ? j + 1 : 0; }
    else jw = 1;  // (0,0) cell uses sentence[1]
    int word = sentence[jw * NB + b];
    const __nv_bfloat16* hwrow = &g_hwb[row * HD];
    float part = 0.f;
    for (int tt = 0; tt < 16; tt++) {
        int h = lane + tt * 32;
        part = fmaf(__bfloat162float(hwrow[h]),
                    __bfloat162float(g_W2wb[h * NV + word]), part);
    }
    for (int o = 16; o; o >>= 1) part += __shfl_xor_sync(0xffffffffu, part, o);
    if (lane == 0) g_gw[row] = part + b2w[word];
}

// ------------------------- DP base cells -------------------------
__global__ void base_kernel() {
    int idx = blockIdx.x * 256 + threadIdx.x;
    if (idx < NP * NB) {
        int p = idx >> 3, b = idx & 7;
        int j;
        int i = inv_pair(p, j);
        if (j <= LL - 2) {
            float lse = logf(g_sum[idx]);
            g_table[((i * LL + j) * LL + (j + 1)) * NB + b] =
                g_shlog[idx] + g_gw[idx] - lse;
        }
    } else if (idx < NP * NB + NB) {
        int b = idx - NP * NB;
        int rr = NP * NB + b;
        g_table[(0 * LL + 1) * NB + b] = g_gw[rr] - logf(g_sum[rr]);
    }
}

// ------------------------- full inside recursion, one persistent launch --------
// 62 blocks (all co-resident: 62 < 148 SMs), global spin barrier per gap.
__global__ void dp_all(float* __restrict__ out) {
    int blk = blockIdx.x;
    int tid = threadIdx.x;
    __shared__ float right[62 * 8];
    for (int gap = 2; gap <= LL - 1; gap++) {
        int nblk = LL - gap;
        if (blk < nblk) {
            int iv = blk;
            int jv = iv + gap;
            int nk = gap - 1;
            for (int m = tid; m < nk * 8; m += 512) {
                int d = m >> 3, b = m & 7;
                int k = iv + 1 + d;
                right[m] = g_table[((iv * LL + k) * LL + jv) * NB + b] +
                           g_relog[pidx(k, jv) * NB + b];
            }
            __syncthreads();
            int b = tid & 7, l = tid >> 3;
            const float* base = &g_table[(l * LL + iv) * LL * NB + b];
            float mx = -3.0e38f, s = 0.f;
            for (int d = 0; d < nk; d++) {
                int k = iv + 1 + d;
                float x = base[k * NB] + right[d * 8 + b];
                if (x > mx) { s = s * __expf(mx - x) + 1.f; mx = x; }
                else s += __expf(x - mx);
            }
            g_table[((l * LL + iv) * LL + jv) * NB + b] = mx + logf(s);
            __syncthreads();   // 'right' reused next gap
        }
        // grid-wide barrier for this gap
        if (tid == 0) {
            __threadfence();
            atomicAdd(&g_bar[gap], 1);
            while (*((volatile int*)&g_bar[gap]) < (int)gridDim.x) {}
            __threadfence();
        }
        __syncthreads();
    }
    if (blk == 0 && tid < NB)
        out[tid] = g_table[(0 * LL + (LL - 1)) * NB + tid];
}

// ------------------------- launch -------------------------
extern "C" void kernel_launch(void* const* d_in, const int* in_sizes, int n_in,
                              void* d_out, int out_size) {
    const float* enc = (const float*)d_in[0];
    const int* sentence = (const int*)d_in[1];
    const float* W1t = (const float*)d_in[2];
    const float* b1t = (const float*)d_in[3];
    const float* W2t = (const float*)d_in[4];
    const float* b2t = (const float*)d_in[5];
    const float* W1w = (const float*)d_in[6];
    const float* b1w = (const float*)d_in[7];
    const float* W2w = (const float*)d_in[8];
    const float* b2w = (const float*)d_in[9];
    float* out = (float*)d_out;

    fill_init<<<8192, 256>>>();
    convertW<<<(HD * NV) / (256 * 4), 256>>>(W2w);

    proj_gemm<<<dim3(8, 8, 4), 256>>>(enc, W1t, W1w);

    pair_kernel<<<NP + 1, 256>>>(b1t, W2t, b2t, b1w);

    gemm_lse_wmma<<<dim3(127, 64), 256>>>(b2w);

    gather_kernel<<<(NROW + 7) / 8, 256>>>(sentence, b2w);
    base_kernel<<<64, 256>>>();

    dp_all<<<62, 512>>>(out);
}

// round 7
// speedup vs baseline: 3.8027x; 1.1081x over previous
#include <cuda_runtime.h>
#include <cuda_bf16.h>
#include <mma.h>
#include <math.h>

#define LL 64
#define NB 8
#define HD 512
#define NV 8192
#define NP 2016                       // L*(L-1)/2 pairs
#define NROW ((NP + 1) * NB)          // 16136 rows (pairs + the (0,0) cell)
#define NROW_PAD (127 * 128)          // 16256, padded to GEMM row tiles
#define NEGV (-1e9f)
#define EPSV 4.5399929762484854e-05f  // exp(-10)

using namespace nvcuda;

// ------------------------- device scratch -------------------------
__device__ float g_At[LL * NB * HD];      // enc @ W1t[:H]
__device__ float g_Bt[LL * NB * HD];      // enc @ W1t[H:]
__device__ float g_Aw[LL * NB * HD];      // enc @ W1w[:H]
__device__ float g_Bw[LL * NB * HD];      // enc @ W1w[H:]
__device__ __nv_bfloat16 g_hwb[NROW_PAD * HD];   // relu hidden (bf16) for word head
__device__ __nv_bfloat16 g_W2wb[HD * NV];        // W2w in bf16
__device__ float g_shlog[NP * NB];        // log1p(-p + EPS)
__device__ float g_relog[NP * NB];        // log(p + EPS)
__device__ float g_sum[NROW_PAD];         // sum of exp(logit) per row
__device__ float g_gw[NROW];              // gathered word logit per row
__device__ float g_table[LL * LL * LL * NB];
__device__ int g_bar[LL];                 // per-gap arrival counters (zeroed each call)

__device__ __forceinline__ int pidx(int i, int j) {
    return i * (2 * LL - 1 - i) / 2 + (j - i - 1);
}

__device__ __forceinline__ int inv_pair(int p, int& j) {
    int i = 0;
    while (p >= (LL - 1 - i)) { p -= (LL - 1 - i); i++; }
    j = i + 1 + p;
    return i;
}

// ------------------------- init + W2w->bf16 (merged, one launch) ---------------
__global__ void init_all(const float* __restrict__ W) {
    int idx = blockIdx.x * 256 + threadIdx.x;
    if (idx < LL * LL * LL * NB) g_table[idx] = NEGV;
    if (idx < NROW_PAD) g_sum[idx] = 0.f;
    if (idx < (NROW_PAD - NROW) * HD) g_hwb[NROW * HD + idx] = __float2bfloat16(0.f);
    if (idx < LL) g_bar[idx] = 0;
    if (idx < (HD * NV) / 4) {
        int i = idx * 4;
        float4 v = *(const float4*)(W + i);
        __nv_bfloat16 o[4];
        o[0] = __float2bfloat16(v.x);
        o[1] = __float2bfloat16(v.y);
        o[2] = __float2bfloat16(v.z);
        o[3] = __float2bfloat16(v.w);
        *(unsigned long long*)(&g_W2wb[i]) = *(unsigned long long*)o;
    }
}

// ------------------------- enc projections (all 4 in one launch) -------------------------
__global__ void proj_gemm(const float* __restrict__ A, const float* __restrict__ W1t,
                          const float* __restrict__ W1w) {
    int which = blockIdx.z;
    const float* W = (which < 2) ? W1t : W1w;
    int koff = (which & 1) * HD;
    float* C = (which == 0) ? g_At : (which == 1) ? g_Bt : (which == 2) ? g_Aw : g_Bw;
    __shared__ float As[16][64];
    __shared__ float Bs[16][64];
    int tid = threadIdx.x;
    int tc = tid & 15, tr = tid >> 4;
    int rb = blockIdx.y * 64, cb = blockIdx.x * 64;
    float acc[4][4];
    for (int i = 0; i < 4; i++)
        for (int q = 0; q < 4; q++) acc[i][q] = 0.f;

    for (int k0 = 0; k0 < HD; k0 += 16) {
        for (int l = tid; l < 1024; l += 256) {
            int r = l >> 4, c = l & 15;
            As[c][r] = A[(rb + r) * HD + k0 + c];
        }
        for (int l = tid; l < 1024; l += 256) {
            int r = l >> 6, c = l & 63;
            Bs[r][c] = W[(koff + k0 + r) * HD + cb + c];
        }
        __syncthreads();
        for (int kk = 0; kk < 16; kk++) {
            float av[4], bv[4];
            for (int i = 0; i < 4; i++) av[i] = As[kk][tr * 4 + i];
            for (int q = 0; q < 4; q++) bv[q] = Bs[kk][tc * 4 + q];
            for (int i = 0; i < 4; i++)
                for (int q = 0; q < 4; q++) acc[i][q] = fmaf(av[i], bv[q], acc[i][q]);
        }
        __syncthreads();
    }
    for (int i = 0; i < 4; i++)
        for (int q = 0; q < 4; q++)
            C[(rb + tr * 4 + i) * HD + cb + tc * 4 + q] = acc[i][q];
}

// ------------------------- per-pair MLP heads -------------------------
__global__ void pair_kernel(const float* __restrict__ b1t, const float* __restrict__ W2t,
                            const float* __restrict__ b2t, const float* __restrict__ b1w) {
    int p = blockIdx.x;
    int i = 0, j = 0;
    if (p < NP) i = inv_pair(p, j);
    int w = threadIdx.x >> 5;
    int lane = threadIdx.x & 31;
    const float* Ar = &g_Aw[(i * NB + w) * HD];
    const float* Br = &g_Bw[(j * NB + w) * HD];
    const float* At = &g_At[(i * NB + w) * HD];
    const float* Bt = &g_Bt[(j * NB + w) * HD];
    __nv_bfloat16* hwrow = &g_hwb[(p * NB + w) * HD];
    float part = 0.f;
    for (int t = 0; t < 16; t++) {
        int h = lane + t * 32;
        float hw = fmaxf(Ar[h] + Br[h] + b1w[h], 0.f);
        hwrow[h] = __float2bfloat16(hw);
        if (p < NP) {
            float ht = fmaxf(At[h] + Bt[h] + b1t[h], 0.f);
            part = fmaf(ht, W2t[h], part);
        }
    }
    if (p < NP) {
        for (int o = 16; o; o >>= 1) part += __shfl_xor_sync(0xffffffffu, part, o);
        if (lane == 0) {
            float z = part + b2t[0];
            float s = 1.f / (1.f + expf(-z));
            g_shlog[p * NB + w] = log1pf(-s + EPSV);
            g_relog[p * NB + w] = logf(s + EPSV);
        }
    }
}

// ------------------------- wmma GEMM + sum(exp), 2-stage smem double buffer ----
// C = hwb[16256,512] @ W2wb[512,8192] (bf16 -> f32); per row accumulate
// sum_v exp(c + b2w[v]) into g_sum via atomicAdd (32 column blocks).
// Tiles: BM=128, BN=256, BK=32. 8 warps as 2 (m) x 4 (n); warp tile 64x64
// = 4 (mt) x 4 (nt) wmma 16x16x16 fragments. One __syncthreads per k-tile.
#define AS_LD 40
#define BS_LD 264
__global__ void __launch_bounds__(256) gemm_lse_wmma(const float* __restrict__ b2w) {
    __shared__ __align__(128) __nv_bfloat16 As[2][128 * AS_LD];
    __shared__ __align__(128) __nv_bfloat16 Bs[2][32 * BS_LD];
    __shared__ __align__(128) float stage[8 * 256];   // 1KB per warp
    int tid = threadIdx.x;
    int wid = tid >> 5, lane = tid & 31;
    int wm = wid >> 2, wn = wid & 3;
    int rowBase = blockIdx.x * 128;
    int v0 = blockIdx.y * 256;

    // per-thread load coordinates
    int ar0 = tid >> 2, ac0 = (tid & 3) * 8;              // A: 512 uint4, 2/thread
    int ar1 = (tid + 256) >> 2, ac1 = ((tid + 256) & 3) * 8;
    int bk[4], bn[4];                                     // B: 1024 uint4, 4/thread
    for (int l = 0; l < 4; l++) {
        int idx = tid + l * 256;
        bk[l] = idx >> 5;
        bn[l] = (idx & 31) * 8;
    }

    wmma::fragment<wmma::accumulator, 16, 16, 16, float> acc[4][4];
    for (int mt = 0; mt < 4; mt++)
        for (int nt = 0; nt < 4; nt++) wmma::fill_fragment(acc[mt][nt], 0.f);

    // prologue: prefetch k-tile 0 into registers
    uint4 pa0 = *(const uint4*)(&g_hwb[(rowBase + ar0) * HD + ac0]);
    uint4 pa1 = *(const uint4*)(&g_hwb[(rowBase + ar1) * HD + ac1]);
    uint4 pb[4];
    for (int l = 0; l < 4; l++)
        pb[l] = *(const uint4*)(&g_W2wb[bk[l] * NV + v0 + bn[l]]);

    int buf = 0;
    for (int kt = 0; kt < 16; kt++) {
        // store the prefetched tile to smem buffer `buf`
        *(uint4*)(&As[buf][ar0 * AS_LD + ac0]) = pa0;
        *(uint4*)(&As[buf][ar1 * AS_LD + ac1]) = pa1;
        for (int l = 0; l < 4; l++)
            *(uint4*)(&Bs[buf][bk[l] * BS_LD + bn[l]]) = pb[l];
        __syncthreads();
        // issue next tile's global loads (overlap with compute below)
        if (kt + 1 < 16) {
            int k0 = (kt + 1) * 32;
            pa0 = *(const uint4*)(&g_hwb[(rowBase + ar0) * HD + k0 + ac0]);
            pa1 = *(const uint4*)(&g_hwb[(rowBase + ar1) * HD + k0 + ac1]);
            for (int l = 0; l < 4; l++)
                pb[l] = *(const uint4*)(&g_W2wb[(k0 + bk[l]) * NV + v0 + bn[l]]);
        }
        for (int kk = 0; kk < 32; kk += 16) {
            wmma::fragment<wmma::matrix_a, 16, 16, 16, __nv_bfloat16, wmma::row_major> af[4];
            wmma::fragment<wmma::matrix_b, 16, 16, 16, __nv_bfloat16, wmma::row_major> bf[4];
            for (int mt = 0; mt < 4; mt++)
                wmma::load_matrix_sync(af[mt], &As[buf][(wm * 64 + mt * 16) * AS_LD + kk], AS_LD);
            for (int nt = 0; nt < 4; nt++)
                wmma::load_matrix_sync(bf[nt], &Bs[buf][kk * BS_LD + wn * 64 + nt * 16], BS_LD);
            for (int mt = 0; mt < 4; mt++)
                for (int nt = 0; nt < 4; nt++)
                    wmma::mma_sync(acc[mt][nt], af[mt], bf[nt], acc[mt][nt]);
        }
        buf ^= 1;   // no trailing sync: next STS targets the other buffer
    }

    // epilogue: stage each 16x16 tile, exp + row-reduce, atomicAdd per row
    float* st = &stage[wid * 256];
    int r = lane & 15, half = lane >> 4;
    float rs[4];
    for (int mt = 0; mt < 4; mt++) rs[mt] = 0.f;
    for (int mt = 0; mt < 4; mt++) {
        for (int nt = 0; nt < 4; nt++) {
            wmma::store_matrix_sync(st, acc[mt][nt], 16, wmma::mem_row_major);
            __syncwarp();
            int cb = v0 + wn * 64 + nt * 16 + half * 8;
            float s = 0.f;
            for (int c = 0; c < 8; c++)
                s += __expf(st[r * 16 + half * 8 + c] + b2w[cb + c]);
            s += __shfl_xor_sync(0xffffffffu, s, 16);
            rs[mt] += s;
            __syncwarp();
        }
    }
    if (lane < 16) {
        for (int mt = 0; mt < 4; mt++)
            atomicAdd(&g_sum[rowBase + wm * 64 + mt * 16 + lane], rs[mt]);
    }
}

// ------------------------- gathered word logit -------------------------
__global__ void gather_kernel(const int* __restrict__ sentence,
                              const float* __restrict__ b2w) {
    int row = blockIdx.x * 8 + (threadIdx.x >> 5);
    int lane = threadIdx.x & 31;
    if (row >= NROW) return;
    int p = row >> 3, b = row & 7;
    int jw;
    if (p < NP) { int j; inv_pair(p, j); jw = (j + 1 < LL) ? j + 1 : 0; }
    else jw = 1;  // (0,0) cell uses sentence[1]
    int word = sentence[jw * NB + b];
    const __nv_bfloat16* hwrow = &g_hwb[row * HD];
    float part = 0.f;
    for (int tt = 0; tt < 16; tt++) {
        int h = lane + tt * 32;
        part = fmaf(__bfloat162float(hwrow[h]),
                    __bfloat162float(g_W2wb[h * NV + word]), part);
    }
    for (int o = 16; o; o >>= 1) part += __shfl_xor_sync(0xffffffffu, part, o);
    if (lane == 0) g_gw[row] = part + b2w[word];
}

// ------------------------- DP base cells -------------------------
__global__ void base_kernel() {
    int idx = blockIdx.x * 256 + threadIdx.x;
    if (idx < NP * NB) {
        int p = idx >> 3, b = idx & 7;
        int j;
        int i = inv_pair(p, j);
        if (j <= LL - 2) {
            float lse = logf(g_sum[idx]);
            g_table[((i * LL + j) * LL + (j + 1)) * NB + b] =
                g_shlog[idx] + g_gw[idx] - lse;
        }
    } else if (idx < NP * NB + NB) {
        int b = idx - NP * NB;
        int rr = NP * NB + b;
        g_table[(0 * LL + 1) * NB + b] = g_gw[rr] - logf(g_sum[rr]);
    }
}

// ------------------------- full inside recursion, one persistent launch --------
// 62 blocks (all co-resident: 62 < 148 SMs), global spin barrier per gap.
__global__ void dp_all(float* __restrict__ out) {
    int blk = blockIdx.x;
    int tid = threadIdx.x;
    __shared__ float right[62 * 8];
    for (int gap = 2; gap <= LL - 1; gap++) {
        int nblk = LL - gap;
        if (blk < nblk) {
            int iv = blk;
            int jv = iv + gap;
            int nk = gap - 1;
            for (int m = tid; m < nk * 8; m += 512) {
                int d = m >> 3, b = m & 7;
                int k = iv + 1 + d;
                right[m] = g_table[((iv * LL + k) * LL + jv) * NB + b] +
                           g_relog[pidx(k, jv) * NB + b];
            }
            __syncthreads();
            int b = tid & 7, l = tid >> 3;
            const float* base = &g_table[(l * LL + iv) * LL * NB + b];
            float mx = -3.0e38f, s = 0.f;
            for (int d = 0; d < nk; d++) {
                int k = iv + 1 + d;
                float x = base[k * NB] + right[d * 8 + b];
                if (x > mx) { s = s * __expf(mx - x) + 1.f; mx = x; }
                else s += __expf(x - mx);
            }
            g_table[((l * LL + iv) * LL + jv) * NB + b] = mx + logf(s);
            __syncthreads();   // 'right' reused next gap
        }
        // grid-wide barrier for this gap
        if (tid == 0) {
            __threadfence();
            atomicAdd(&g_bar[gap], 1);
            while (*((volatile int*)&g_bar[gap]) < (int)gridDim.x) {}
            __threadfence();
        }
        __syncthreads();
    }
    if (blk == 0 && tid < NB)
        out[tid] = g_table[(0 * LL + (LL - 1)) * NB + tid];
}

// ------------------------- launch -------------------------
extern "C" void kernel_launch(void* const* d_in, const int* in_sizes, int n_in,
                              void* d_out, int out_size) {
    const float* enc = (const float*)d_in[0];
    const int* sentence = (const int*)d_in[1];
    const float* W1t = (const float*)d_in[2];
    const float* b1t = (const float*)d_in[3];
    const float* W2t = (const float*)d_in[4];
    const float* b2t = (const float*)d_in[5];
    const float* W1w = (const float*)d_in[6];
    const float* b1w = (const float*)d_in[7];
    const float* W2w = (const float*)d_in[8];
    const float* b2w = (const float*)d_in[9];
    float* out = (float*)d_out;

    init_all<<<8192, 256>>>(W2w);                       // launch 1
    proj_gemm<<<dim3(8, 8, 4), 256>>>(enc, W1t, W1w);   // launch 2
    pair_kernel<<<NP + 1, 256>>>(b1t, W2t, b2t, b1w);   // launch 3
    gemm_lse_wmma<<<dim3(127, 32), 256>>>(b2w);         // launch 4  (ncu target)
    gather_kernel<<<(NROW + 7) / 8, 256>>>(sentence, b2w);
    base_kernel<<<64, 256>>>();
    dp_all<<<62, 512>>>(out);
}